// round 8
// baseline (speedup 1.0000x reference)
#include <cuda_runtime.h>
#include <cuda_bf16.h>

// ---------------------------------------------------------------------------
// Problem constants
// ---------------------------------------------------------------------------
#define LAYERS 4
#define NC 3
#define D1 48
#define D2 48
#define D3 48
#define D4 24
#define NSP  (D1*D2*D3*D4)        // 2,654,208 spatial points per channel
#define CN   (NC*NSP)             // 7,962,624 elems per batch image

// Scratch: batch-interleaved tensors, float2 = {b0, b1}
__device__ float2 s_fi[CN];
__device__ float2 s_bi[CN];
__device__ float2 s_g [CN];
__device__ float2 s_t [CN];
__device__ float2 s_oA[CN];
__device__ float2 s_oB[CN];
// Winograd-transformed Wg weights: [layer][ci][k123][co][p0..7], dup'd f2
__device__ float2 s_wgt[LAYERS*6*27*3*8];

// ---- packed f32x2 ops ------------------------------------------------------
__device__ __forceinline__ float2 ffma2(float2 a, float2 b, float2 c) {
    unsigned long long ua, ub, uc, ud;
    ua = *reinterpret_cast<const unsigned long long*>(&a);
    ub = *reinterpret_cast<const unsigned long long*>(&b);
    uc = *reinterpret_cast<const unsigned long long*>(&c);
    asm("fma.rn.f32x2 %0, %1, %2, %3;" : "=l"(ud) : "l"(ua), "l"(ub), "l"(uc));
    return *reinterpret_cast<float2*>(&ud);
}
__device__ __forceinline__ float2 fadd2(float2 a, float2 b) {
    unsigned long long ua, ub, ud;
    ua = *reinterpret_cast<const unsigned long long*>(&a);
    ub = *reinterpret_cast<const unsigned long long*>(&b);
    asm("add.rn.f32x2 %0, %1, %2;" : "=l"(ud) : "l"(ua), "l"(ub));
    return *reinterpret_cast<float2*>(&ud);
}
__device__ __forceinline__ float2 fsub2(float2 a, float2 b) {   // a - b
    return ffma2(b, make_float2(-1.f, -1.f), a);
}

__global__ void dummy_kernel() {}

// ---------------------------------------------------------------------------
// Pack f / boundary into interleaved layout
// ---------------------------------------------------------------------------
__global__ void pack_kernel(const float4* __restrict__ f,
                            const float4* __restrict__ bnd,
                            float4* __restrict__ fi,
                            float4* __restrict__ bi) {
    int i = blockIdx.x * blockDim.x + threadIdx.x;
    if (i >= CN / 4) return;
    float4 a = f[i],   b = f[i + CN / 4];
    fi[2*i]     = make_float4(a.x, b.x, a.y, b.y);
    fi[2*i + 1] = make_float4(a.z, b.z, a.w, b.w);
    a = bnd[i]; b = bnd[i + CN / 4];
    bi[2*i]     = make_float4(a.x, b.x, a.y, b.y);
    bi[2*i + 1] = make_float4(a.z, b.z, a.w, b.w);
}

// ---------------------------------------------------------------------------
// Weight transform (G w) for all layers/ci/k123/co: 3 taps -> 8 points.
// F(6,3), points {0, ±1, ±2, ±1/2, inf} (ACL/oneDNN standard, verified).
// ---------------------------------------------------------------------------
__global__ void wgw_kernel(const float* __restrict__ Wg) {
    int idx = blockIdx.x * blockDim.x + threadIdx.x;   // [L][ci][k123][co]
    if (idx >= LAYERS*6*27*3) return;
    int co = idx % 3;  int r = idx / 3;
    int k123 = r % 27; r /= 27;
    int ci = r % 6;    int L = r / 6;
    const float* w = Wg + L*1458 + (co*6 + ci)*81 + k123*3;
    float w0 = w[0], w1 = w[1], w2 = w[2];
    float p[8];
    p[0] = w0;
    p[1] = (-2.f/9.f)  * (w0 + w1 + w2);
    p[2] = (-2.f/9.f)  * (w0 - w1 + w2);
    p[3] = (1.f/90.f)*w0 + (1.f/45.f)*w1 + (2.f/45.f)*w2;
    p[4] = (1.f/90.f)*w0 - (1.f/45.f)*w1 + (2.f/45.f)*w2;
    p[5] = (32.f/45.f)*w0 + (16.f/45.f)*w1 + (8.f/45.f)*w2;
    p[6] = (32.f/45.f)*w0 - (16.f/45.f)*w1 + (8.f/45.f)*w2;
    p[7] = w2;
    float2* o = s_wgt + idx*8;
    #pragma unroll
    for (int m = 0; m < 8; ++m) o[m] = make_float2(p[m], p[m]);
}

// ---------------------------------------------------------------------------
// Wg conv via Winograd F(6,3) along x4.
// Tile x1=2, x2=4, x3=8, x4=24 (4 groups of 6). 256 threads; thread owns
// (x1l,x2l,x3l, group q) and 3co x 8 transformed-point accumulators.
// smem: per-ci weight slice [27][3][8] f2 + transformed stage [240 rows][34 f2]
// (group g at cols g*8..g*8+7; stride 17 f4 odd -> conflict-free LDS.128).
// ---------------------------------------------------------------------------
#define WG_WSL_F2   (27*3*8)                      // 648 f2
#define WG_STAGE_F2 (240*34)                      // 8160 f2
#define WG_SMEM     ((WG_WSL_F2 + WG_STAGE_F2)*8) // 70464 B -> 3 blocks/SM

__global__ __launch_bounds__(256, 3) void wg_kernel(
    const float2* __restrict__ inA, const float2* __restrict__ inB,
    const float2* __restrict__ wgt,   // transformed weights, this layer
    const float*  __restrict__ bias,
    float2* __restrict__ out)
{
    extern __shared__ float2 dsm[];
    float2* sW  = dsm;                 // [k123][co][8]
    float2* sIn = dsm + WG_WSL_F2;     // [240][34]

    const int tid = threadIdx.x;
    const int x3l = tid & 7;
    const int q   = (tid >> 3) & 3;    // output group: x4 = q*6 .. q*6+5
    const int x2l = (tid >> 5) & 3;
    const int x1l = tid >> 7;
    const int x1g = blockIdx.x * 2;
    const int x2g = blockIdx.y * 4;
    const int x3g = blockIdx.z * 8;

    float2 acc[3][8];
    #pragma unroll
    for (int co = 0; co < 3; ++co)
        #pragma unroll
        for (int m = 0; m < 8; ++m) acc[co][m] = make_float2(0.f, 0.f);

    const float2 z = make_float2(0.f, 0.f);

    for (int ci = 0; ci < 6; ++ci) {
        const float2* __restrict__ src =
            (ci < 3) ? (inA + ci * NSP) : (inB + (ci - 3) * NSP);
        __syncthreads();
        // per-ci weight slice -> smem (648 f2 = 324 f4)
        {
            const float4* wsrc = (const float4*)(wgt + ci * WG_WSL_F2);
            for (int s = tid; s < 324; s += 256)
                ((float4*)sW)[s] = wsrc[s];
        }
        // stage: load raw group (8 f2), transform B^T, store to sIn
        for (int it = tid; it < 960; it += 256) {
            int r = it >> 2, g = it & 3;
            int p3 = r % 10; int t = r / 10; int p2 = t % 6; int p1 = t / 6;
            int g1 = x1g - 1 + p1, g2 = x2g - 1 + p2, g3 = x3g - 1 + p3;
            bool rowok = ((unsigned)g1 < (unsigned)D1 &&
                          (unsigned)g2 < (unsigned)D2 &&
                          (unsigned)g3 < (unsigned)D3);
            const float2* rp = src + ((g1*D2 + g2)*D3 + g3)*D4;
            float2 x[8];
            #pragma unroll
            for (int e = 0; e < 8; ++e) {
                int x4 = 6*g - 1 + e;
                x[e] = (rowok && (unsigned)x4 < (unsigned)D4) ? rp[x4] : z;
            }
            // B^T x  (even/odd decomposition)
            const float2 c425  = make_float2( 4.25f,  4.25f);
            const float2 c525  = make_float2( 5.25f,  5.25f);
            float2 u[8];
            u[0] = ffma2(fsub2(x[4], x[2]), c525, fsub2(x[0], x[6]));
            u[7] = ffma2(fsub2(x[3], x[5]), c525, fsub2(x[7], x[1]));
            {   // u1/u2: e = x2+x6-4.25 x4 ; o = x1+x5-4.25 x3
                float2 e = ffma2(x[4], make_float2(-4.25f,-4.25f), fadd2(x[2], x[6]));
                float2 o = ffma2(x[3], make_float2(-4.25f,-4.25f), fadd2(x[1], x[5]));
                u[1] = fadd2(e, o);
                u[2] = fsub2(e, o);
            }
            {   // u3/u4: e = 0.25 x2 -1.25 x4 + x6 ; o = 0.5 x1 -2.5 x3 + 2 x5
                float2 e = ffma2(x[2], make_float2(0.25f,0.25f),
                           ffma2(x[4], make_float2(-1.25f,-1.25f), x[6]));
                float2 o = ffma2(x[1], make_float2(0.5f,0.5f),
                           ffma2(x[3], make_float2(-2.5f,-2.5f),
                           ffma2(x[5], make_float2(2.f,2.f), z)));
                u[3] = fadd2(e, o);
                u[4] = fsub2(e, o);
            }
            {   // u5/u6: e = 4 x2 -5 x4 + x6 ; o = 2 x1 -2.5 x3 + 0.5 x5
                float2 e = ffma2(x[2], make_float2(4.f,4.f),
                           ffma2(x[4], make_float2(-5.f,-5.f), x[6]));
                float2 o = ffma2(x[1], make_float2(2.f,2.f),
                           ffma2(x[3], make_float2(-2.5f,-2.5f),
                           ffma2(x[5], make_float2(0.5f,0.5f), z)));
                u[5] = fadd2(e, o);
                u[6] = fsub2(e, o);
            }
            float4* sp = (float4*)sIn + (r*17 + g*4);
            #pragma unroll
            for (int m = 0; m < 4; ++m)
                sp[m] = make_float4(u[2*m].x, u[2*m].y, u[2*m+1].x, u[2*m+1].y);
        }
        __syncthreads();

        // elementwise accumulation in transformed domain
        #pragma unroll 1
        for (int k1 = 0; k1 < 3; ++k1) {
            #pragma unroll
            for (int k23 = 0; k23 < 9; ++k23) {
                const int k2 = k23 / 3, k3 = k23 % 3;
                const float4* up = (const float4*)sIn
                    + (((x1l + k1)*6 + (x2l + k2))*10 + (x3l + k3))*17 + q*4;
                float4 ua[4];
                #pragma unroll
                for (int m = 0; m < 4; ++m) ua[m] = up[m];
                const float2* uf = reinterpret_cast<const float2*>(ua);

                const float4* wp = (const float4*)(sW + (k1*9 + k23)*24);
                #pragma unroll
                for (int co = 0; co < 3; ++co) {
                    #pragma unroll
                    for (int pp = 0; pp < 4; ++pp) {
                        float4 wv = wp[co*4 + pp];
                        acc[co][2*pp]   = ffma2(uf[2*pp],
                            make_float2(wv.x, wv.y), acc[co][2*pp]);
                        acc[co][2*pp+1] = ffma2(uf[2*pp+1],
                            make_float2(wv.z, wv.w), acc[co][2*pp+1]);
                    }
                }
            }
        }
    }

    // inverse transform A^T m + bias, store 6 outputs per co
    const int x1 = x1g + x1l, x2 = x2g + x2l, x3 = x3g + x3l;
    const int base = ((x1*D2 + x2)*D3 + x3)*D4 + q*6;
    #pragma unroll
    for (int co = 0; co < 3; ++co) {
        float bsc = __ldg(bias + co);
        float2 bb = make_float2(bsc, bsc);
        float2* m = acc[co];
        float2 s1 = fadd2(m[1], m[2]), d1 = fsub2(m[1], m[2]);
        float2 s3 = fadd2(m[3], m[4]), d3 = fsub2(m[3], m[4]);
        float2 s5 = fadd2(m[5], m[6]), d5 = fsub2(m[5], m[6]);
        float2 y[6];
        y[0] = fadd2(fadd2(fadd2(m[0], s1), fadd2(s3, s5)), bb);
        y[1] = ffma2(d3, make_float2(2.f,2.f),
               ffma2(d5, make_float2(0.5f,0.5f), fadd2(d1, bb)));
        y[2] = ffma2(s3, make_float2(4.f,4.f),
               ffma2(s5, make_float2(0.25f,0.25f), fadd2(s1, bb)));
        y[3] = ffma2(d3, make_float2(8.f,8.f),
               ffma2(d5, make_float2(0.125f,0.125f), fadd2(d1, bb)));
        y[4] = ffma2(s3, make_float2(16.f,16.f),
               ffma2(s5, make_float2(0.0625f,0.0625f), fadd2(s1, bb)));
        y[5] = ffma2(d3, make_float2(32.f,32.f),
               ffma2(d5, make_float2(0.03125f,0.03125f),
               fadd2(fadd2(d1, m[7]), bb)));
        float4* op = (float4*)(out + co*NSP + base);
        #pragma unroll
        for (int j2 = 0; j2 < 3; ++j2)
            op[j2] = make_float4(y[2*j2].x, y[2*j2].y,
                                 y[2*j2+1].x, y[2*j2+1].y);
    }
}

// ---------------------------------------------------------------------------
// W1 conv: 3->3 ch, (3,3,3,1) taps, pad (1,1,1,0)  [UNCHANGED — R7 passing]
// ---------------------------------------------------------------------------
#define W1_W_F2     (81*4)
#define W1_STAGE_F2 (240*26)
#define W1_SMEM     ((W1_W_F2 + W1_STAGE_F2)*8)    // 52512 B

__global__ __launch_bounds__(256, 3) void w1_kernel(
    const float2* __restrict__ g,
    const float*  __restrict__ W,  const float* __restrict__ bias,
    float2* __restrict__ out)
{
    extern __shared__ float2 dsm[];
    float2* sW  = dsm;
    float2* sIn = dsm + W1_W_F2;

    const int tid = threadIdx.x;
    const int x3l = tid & 7;
    const int q   = (tid >> 3) & 3;
    const int x2l = (tid >> 5) & 3;
    const int x1l = tid >> 7;
    const int x1g = blockIdx.x * 2;
    const int x2g = blockIdx.y * 4;
    const int x3g = blockIdx.z * 8;

    for (int s = tid; s < 81*3; s += 256) {
        int grp = s / 3, co = s % 3;
        int ci = grp / 27, k = grp % 27;
        float w = W[(co*3 + ci)*27 + k];
        sW[grp*4 + co] = make_float2(w, w);
    }

    float2 acc[3][6];
    #pragma unroll
    for (int co = 0; co < 3; ++co) {
        float b = __ldg(bias + co);
        #pragma unroll
        for (int j = 0; j < 6; ++j) acc[co][j] = make_float2(b, b);
    }

    for (int ci = 0; ci < 3; ++ci) {
        const float2* __restrict__ src = g + ci * NSP;
        __syncthreads();
        for (int idx = tid; idx < 240*12; idx += 256) {
            int row = idx / 12, c = idx % 12;
            int p3 = row % 10; int t = row / 10; int p2 = t % 6; int p1 = t / 6;
            int g1 = x1g - 1 + p1, g2 = x2g - 1 + p2, g3 = x3g - 1 + p3;
            float4 v = make_float4(0.f, 0.f, 0.f, 0.f);
            if ((unsigned)g1 < (unsigned)D1 && (unsigned)g2 < (unsigned)D2 &&
                (unsigned)g3 < (unsigned)D3)
                v = ((const float4*)src)[((g1*D2 + g2)*D3 + g3)*12 + c];
            ((float4*)sIn)[row*13 + c] = v;
        }
        __syncthreads();

        const float2* wci = sW + ci * 108;
        #pragma unroll 1
        for (int k1 = 0; k1 < 3; ++k1) {
            #pragma unroll
            for (int k23 = 0; k23 < 9; ++k23) {
                const int k2 = k23 / 3, k3 = k23 % 3;
                const float4* ip = (const float4*)sIn
                    + (((x1l + k1)*6 + (x2l + k2))*10 + (x3l + k3))*13 + q*3;
                float4 a4[3];
                #pragma unroll
                for (int m = 0; m < 3; ++m) a4[m] = ip[m];
                const float2* uf = reinterpret_cast<const float2*>(a4);

                const float2* wp = wci + (k1*9 + k23)*4;
                float2 w0 = wp[0];
                float2 w1 = wp[1];
                float2 w2 = wp[2];
                #pragma unroll
                for (int j = 0; j < 6; ++j) {
                    acc[0][j] = ffma2(uf[j], w0, acc[0][j]);
                    acc[1][j] = ffma2(uf[j], w1, acc[1][j]);
                    acc[2][j] = ffma2(uf[j], w2, acc[2][j]);
                }
            }
        }
    }

    const int x1 = x1g + x1l, x2 = x2g + x2l, x3 = x3g + x3l;
    const int base = ((x1*D2 + x2)*D3 + x3)*D4 + q*6;
    #pragma unroll
    for (int co = 0; co < 3; ++co) {
        float4* op = (float4*)(out + co*NSP + base);
        #pragma unroll
        for (int j2 = 0; j2 < 3; ++j2)
            op[j2] = make_float4(acc[co][2*j2].x,   acc[co][2*j2].y,
                                 acc[co][2*j2+1].x, acc[co][2*j2+1].y);
    }
}

// ---------------------------------------------------------------------------
// Fused epilogue  [UNCHANGED — passing since R1]
// ---------------------------------------------------------------------------
__global__ void w2wd_kernel(
    const float2* __restrict__ t,  const float2* __restrict__ op,
    const float*  __restrict__ W2, const float* __restrict__ b2,
    const float*  __restrict__ Wd, const float* __restrict__ bd,
    float2* __restrict__ onew, float* __restrict__ ofinal, int final_layer)
{
    int i = blockIdx.x * blockDim.x + threadIdx.x;
    if (i >= NSP) return;
    int x4 = i % D4;

    float w2r[3][3][3], wdr[3][3];
    #pragma unroll
    for (int co = 0; co < 3; ++co) {
        #pragma unroll
        for (int ci = 0; ci < 3; ++ci) {
            #pragma unroll
            for (int k = 0; k < 3; ++k)
                w2r[co][ci][k] = W2[(co*3 + ci)*3 + k];
            wdr[co][ci] = Wd[co*3 + ci];
        }
    }

    float2 acc[3];
    #pragma unroll
    for (int co = 0; co < 3; ++co) {
        float b = b2[co] + bd[co];
        acc[co] = make_float2(b, b);
    }

    const float2 z = make_float2(0.f, 0.f);
    #pragma unroll
    for (int ci = 0; ci < 3; ++ci) {
        float2 tm = (x4 > 0)      ? t[ci*NSP + i - 1] : z;
        float2 t0 =                 t[ci*NSP + i];
        float2 tp = (x4 < D4 - 1) ? t[ci*NSP + i + 1] : z;
        float2 ov =                 op[ci*NSP + i];
        #pragma unroll
        for (int co = 0; co < 3; ++co) {
            float2 a = acc[co];
            a = ffma2(tm, make_float2(w2r[co][ci][0], w2r[co][ci][0]), a);
            a = ffma2(t0, make_float2(w2r[co][ci][1], w2r[co][ci][1]), a);
            a = ffma2(tp, make_float2(w2r[co][ci][2], w2r[co][ci][2]), a);
            a = ffma2(ov, make_float2(wdr[co][ci],    wdr[co][ci]),    a);
            acc[co] = a;
        }
    }

    if (final_layer) {
        #pragma unroll
        for (int co = 0; co < 3; ++co) {
            ofinal[co*NSP + i]      = acc[co].x;
            ofinal[CN + co*NSP + i] = acc[co].y;
        }
    } else {
        #pragma unroll
        for (int co = 0; co < 3; ++co)
            onew[co*NSP + i] = acc[co];
    }
}

// ---------------------------------------------------------------------------
// Driver
// ---------------------------------------------------------------------------
extern "C" void kernel_launch(void* const* d_in, const int* in_sizes, int n_in,
                              void* d_out, int out_size)
{
    const float* f   = (const float*)d_in[0];
    const float* bnd = (const float*)d_in[1];
    const float* Wg  = (const float*)d_in[2];
    const float* bg  = (const float*)d_in[3];
    const float* W1  = (const float*)d_in[4];
    const float* b1  = (const float*)d_in[5];
    const float* W2  = (const float*)d_in[6];
    const float* b2  = (const float*)d_in[7];
    const float* Wd  = (const float*)d_in[8];
    const float* bd  = (const float*)d_in[9];

    static bool attr_done = false;
    if (!attr_done) {
        cudaFuncSetAttribute(wg_kernel,
            cudaFuncAttributeMaxDynamicSharedMemorySize, WG_SMEM);
        cudaFuncSetAttribute(w1_kernel,
            cudaFuncAttributeMaxDynamicSharedMemorySize, W1_SMEM);
        attr_done = true;
    }

    float2 *fi, *bi, *gg, *tt, *oA, *oB, *wt;
    cudaGetSymbolAddress((void**)&fi, s_fi);
    cudaGetSymbolAddress((void**)&bi, s_bi);
    cudaGetSymbolAddress((void**)&gg, s_g);
    cudaGetSymbolAddress((void**)&tt, s_t);
    cudaGetSymbolAddress((void**)&oA, s_oA);
    cudaGetSymbolAddress((void**)&oB, s_oB);
    cudaGetSymbolAddress((void**)&wt, s_wgt);

    pack_kernel<<<(CN/4 + 255) / 256, 256>>>(
        (const float4*)f, (const float4*)bnd, (float4*)fi, (float4*)bi);
    wgw_kernel<<<8, 256>>>(Wg);

    // ncu alignment: harness(2) + pack + wgw + dummy => first wg at slot 6
    dummy_kernel<<<1, 32>>>();

    dim3 cgrid(D1/2, D2/4, D3/8);
    const float2* cur = fi;
    float2* outs[LAYERS] = {oA, oB, oA, nullptr};

    for (int i = 0; i < LAYERS; ++i) {
        wg_kernel<<<cgrid, 256, WG_SMEM>>>(
            cur, bi, wt + i*(6*27*3*8), bg + i*3, gg);
        w1_kernel<<<cgrid, 256, W1_SMEM>>>(
            gg, W1 + i*243, b1 + i*3, tt);
        w2wd_kernel<<<(NSP + 255) / 256, 256>>>(
            tt, cur, W2 + i*27, b2 + i*3, Wd + i*9, bd + i*3,
            outs[i], (float*)d_out, (i == LAYERS - 1) ? 1 : 0);
        cur = outs[i];
    }
}

// round 9
// speedup vs baseline: 1.8998x; 1.8998x over previous
#include <cuda_runtime.h>
#include <cuda_bf16.h>

// ---------------------------------------------------------------------------
// Problem constants
// ---------------------------------------------------------------------------
#define LAYERS 4
#define NC 3
#define D1 48
#define D2 48
#define D3 48
#define D4 24
#define NROW (D1*D2*D3)           // 110,592 x4-rows per channel
#define NSP  (D1*D2*D3*D4)        // 2,654,208 spatial points per channel
#define CN   (NC*NSP)             // 7,962,624 elems per batch image

// Scratch: batch-interleaved tensors, float2 = {b0, b1}
__device__ float2 s_fi[CN];
__device__ float2 s_bi[CN];
__device__ float2 s_g [CN];
__device__ float2 s_t [CN];
__device__ float2 s_oA[CN];
__device__ float2 s_oB[CN];
// x4-Winograd-transformed inputs: [ci 0..5][row][group*8+point] f2
__device__ float2 s_u[6*(size_t)NROW*32];
// Winograd-transformed Wg weights, scalar: [L][ci][k123][co*8+p]
__device__ float s_wgtf[LAYERS*6*27*24];

// ---- packed f32x2 ops ------------------------------------------------------
__device__ __forceinline__ float2 ffma2(float2 a, float2 b, float2 c) {
    unsigned long long ua, ub, uc, ud;
    ua = *reinterpret_cast<const unsigned long long*>(&a);
    ub = *reinterpret_cast<const unsigned long long*>(&b);
    uc = *reinterpret_cast<const unsigned long long*>(&c);
    asm("fma.rn.f32x2 %0, %1, %2, %3;" : "=l"(ud) : "l"(ua), "l"(ub), "l"(uc));
    return *reinterpret_cast<float2*>(&ud);
}
__device__ __forceinline__ float2 fadd2(float2 a, float2 b) {
    unsigned long long ua, ub, ud;
    ua = *reinterpret_cast<const unsigned long long*>(&a);
    ub = *reinterpret_cast<const unsigned long long*>(&b);
    asm("add.rn.f32x2 %0, %1, %2;" : "=l"(ud) : "l"(ua), "l"(ub));
    return *reinterpret_cast<float2*>(&ud);
}
__device__ __forceinline__ float2 fsub2(float2 a, float2 b) {   // a - b
    return ffma2(b, make_float2(-1.f, -1.f), a);
}

// ---------------------------------------------------------------------------
// Pack (+ folded Wg weight transform: G w, F(6,3) points {0,±1,±2,±1/2,inf})
// ---------------------------------------------------------------------------
__global__ void pack_kernel(const float4* __restrict__ f,
                            const float4* __restrict__ bnd,
                            float4* __restrict__ fi,
                            float4* __restrict__ bi,
                            const float* __restrict__ Wg,
                            float* __restrict__ wtf) {
    int i = blockIdx.x * blockDim.x + threadIdx.x;
    if (i < LAYERS*6*27*3) {                 // weight transform (1944 threads)
        int co = i % 3;  int r = i / 3;
        int k123 = r % 27; r /= 27;
        int ci = r % 6;    int L = r / 6;
        const float* w = Wg + L*1458 + (co*6 + ci)*81 + k123*3;
        float w0 = w[0], w1 = w[1], w2 = w[2];
        float p[8];
        p[0] = w0;
        p[1] = (-2.f/9.f)  * (w0 + w1 + w2);
        p[2] = (-2.f/9.f)  * (w0 - w1 + w2);
        p[3] = (1.f/90.f)*w0 + (1.f/45.f)*w1 + (2.f/45.f)*w2;
        p[4] = (1.f/90.f)*w0 - (1.f/45.f)*w1 + (2.f/45.f)*w2;
        p[5] = (32.f/45.f)*w0 + (16.f/45.f)*w1 + (8.f/45.f)*w2;
        p[6] = (32.f/45.f)*w0 - (16.f/45.f)*w1 + (8.f/45.f)*w2;
        p[7] = w2;
        float* o = wtf + ((L*6 + ci)*27 + k123)*24 + co*8;
        #pragma unroll
        for (int m = 0; m < 8; ++m) o[m] = p[m];
    }
    if (i >= CN / 4) return;
    float4 a = f[i],   b = f[i + CN / 4];
    fi[2*i]     = make_float4(a.x, b.x, a.y, b.y);
    fi[2*i + 1] = make_float4(a.z, b.z, a.w, b.w);
    a = bnd[i]; b = bnd[i + CN / 4];
    bi[2*i]     = make_float4(a.x, b.x, a.y, b.y);
    bi[2*i + 1] = make_float4(a.z, b.z, a.w, b.w);
}

// ---------------------------------------------------------------------------
// x4 input transform (B^T), 3 channels per call, global -> global.
// Block: 64 rows; coalesced raw stage -> per-(row,group) transform -> STG.128.
// x4 halo is zero padding (pad=1), handled here; g1g2g3 halo handled in wg.
// ---------------------------------------------------------------------------
__global__ __launch_bounds__(256) void bx_kernel(
    const float2* __restrict__ src,   // 3 channels, [ch][row][24] f2
    float2* __restrict__ dst)         // 3 channels, [ch][row][32] f2
{
    __shared__ float4 sraw[64*13];
    const int ch   = blockIdx.y;
    const int row0 = blockIdx.x * 64;
    const float4* s = (const float4*)(src + (size_t)ch*NSP + (size_t)row0*D4);
    for (int idx = threadIdx.x; idx < 768; idx += 256) {
        int r = idx / 12, c = idx % 12;
        sraw[r*13 + c] = s[idx];
    }
    __syncthreads();

    const int r = threadIdx.x >> 2, g = threadIdx.x & 3;
    const float2* rp = (const float2*)&sraw[r*13];
    const float2 z = make_float2(0.f, 0.f);
    float2 x[8];
    #pragma unroll
    for (int e = 0; e < 8; ++e) {
        int x4 = 6*g - 1 + e;
        x[e] = ((unsigned)x4 < (unsigned)D4) ? rp[x4] : z;
    }
    // B^T x (even/odd decomposition) — validated in R8
    float2 u[8];
    u[0] = ffma2(fsub2(x[4], x[2]), make_float2(5.25f,5.25f), fsub2(x[0], x[6]));
    u[7] = ffma2(fsub2(x[3], x[5]), make_float2(5.25f,5.25f), fsub2(x[7], x[1]));
    {
        float2 e = ffma2(x[4], make_float2(-4.25f,-4.25f), fadd2(x[2], x[6]));
        float2 o = ffma2(x[3], make_float2(-4.25f,-4.25f), fadd2(x[1], x[5]));
        u[1] = fadd2(e, o);
        u[2] = fsub2(e, o);
    }
    {
        float2 e = ffma2(x[2], make_float2(0.25f,0.25f),
                   ffma2(x[4], make_float2(-1.25f,-1.25f), x[6]));
        float2 o = ffma2(x[1], make_float2(0.5f,0.5f),
                   ffma2(x[3], make_float2(-2.5f,-2.5f),
                   ffma2(x[5], make_float2(2.f,2.f), z)));
        u[3] = fadd2(e, o);
        u[4] = fsub2(e, o);
    }
    {
        float2 e = ffma2(x[2], make_float2(4.f,4.f),
                   ffma2(x[4], make_float2(-5.f,-5.f), x[6]));
        float2 o = ffma2(x[1], make_float2(2.f,2.f),
                   ffma2(x[3], make_float2(-2.5f,-2.5f),
                   ffma2(x[5], make_float2(0.5f,0.5f), z)));
        u[5] = fadd2(e, o);
        u[6] = fsub2(e, o);
    }
    float4* d = (float4*)(dst + ((size_t)(ch*NROW + row0 + r))*32) + g*4;
    #pragma unroll
    for (int m = 0; m < 4; ++m)
        d[m] = make_float4(u[2*m].x, u[2*m].y, u[2*m+1].x, u[2*m+1].y);
}

// ---------------------------------------------------------------------------
// Wg conv in Winograd(x4) domain. Tile x1=2,x2=4,x3=8; 256 thr; thread owns
// (spatial, group q), acc[3co][8pt]. Stage transformed rows coalesced from
// the u buffer ([240 rows][16 f4], stride 17 -> conflict-free); weights
// scalar from smem, per-co 2x LDS.128 broadcast.
// ---------------------------------------------------------------------------
#define WG_SMEM (240*17*16 + 648*4)   // 65280 + 2592 = 67872 B

__global__ __launch_bounds__(256, 2) void wg_kernel(
    const float2* __restrict__ ubuf,  // 6 ch transformed
    const float*  __restrict__ wgt,   // this layer: [ci][k123][co*8+p]
    const float*  __restrict__ bias,
    float2* __restrict__ out)
{
    extern __shared__ float4 dsm4[];
    float4* sIn = dsm4;                       // [240][17]
    float*  sWf = (float*)(dsm4 + 240*17);    // [27][24]

    const int tid = threadIdx.x;
    const int x3l = tid & 7;
    const int q   = (tid >> 3) & 3;
    const int x2l = (tid >> 5) & 3;
    const int x1l = tid >> 7;
    const int x1g = blockIdx.x * 2;
    const int x2g = blockIdx.y * 4;
    const int x3g = blockIdx.z * 8;

    float2 acc[3][8];
    #pragma unroll
    for (int co = 0; co < 3; ++co)
        #pragma unroll
        for (int m = 0; m < 8; ++m) acc[co][m] = make_float2(0.f, 0.f);

    for (int ci = 0; ci < 6; ++ci) {
        const float4* __restrict__ usrc =
            (const float4*)(ubuf + (size_t)ci*NROW*32);
        __syncthreads();
        // weights for this ci: 648 floats = 162 f4
        {
            const float4* wsrc = (const float4*)(wgt + ci*648);
            for (int s = tid; s < 162; s += 256)
                ((float4*)sWf)[s] = wsrc[s];
        }
        // stage 240 transformed rows (16 f4 each), zero outside volume
        for (int idx = tid; idx < 240*16; idx += 256) {
            int r = idx >> 4, c = idx & 15;
            int p3 = r % 10; int t = r / 10; int p2 = t % 6; int p1 = t / 6;
            int g1 = x1g - 1 + p1, g2 = x2g - 1 + p2, g3 = x3g - 1 + p3;
            float4 v = make_float4(0.f, 0.f, 0.f, 0.f);
            if ((unsigned)g1 < (unsigned)D1 && (unsigned)g2 < (unsigned)D2 &&
                (unsigned)g3 < (unsigned)D3)
                v = usrc[(size_t)((g1*D2 + g2)*D3 + g3)*16 + c];
            sIn[r*17 + c] = v;
        }
        __syncthreads();

        #pragma unroll 1
        for (int k1 = 0; k1 < 3; ++k1) {
            #pragma unroll
            for (int k23 = 0; k23 < 9; ++k23) {
                const int k2 = k23 / 3, k3 = k23 % 3;
                const float4* up = sIn
                    + (((x1l + k1)*6 + (x2l + k2))*10 + (x3l + k3))*17 + q*4;
                float4 ua[4];
                #pragma unroll
                for (int m = 0; m < 4; ++m) ua[m] = up[m];
                const float2* uf = reinterpret_cast<const float2*>(ua);

                const float4* wp = (const float4*)(sWf + (k1*9 + k23)*24);
                #pragma unroll
                for (int co = 0; co < 3; ++co) {
                    float4 wa = wp[co*2];
                    float4 wb = wp[co*2 + 1];
                    acc[co][0] = ffma2(uf[0], make_float2(wa.x,wa.x), acc[co][0]);
                    acc[co][1] = ffma2(uf[1], make_float2(wa.y,wa.y), acc[co][1]);
                    acc[co][2] = ffma2(uf[2], make_float2(wa.z,wa.z), acc[co][2]);
                    acc[co][3] = ffma2(uf[3], make_float2(wa.w,wa.w), acc[co][3]);
                    acc[co][4] = ffma2(uf[4], make_float2(wb.x,wb.x), acc[co][4]);
                    acc[co][5] = ffma2(uf[5], make_float2(wb.y,wb.y), acc[co][5]);
                    acc[co][6] = ffma2(uf[6], make_float2(wb.z,wb.z), acc[co][6]);
                    acc[co][7] = ffma2(uf[7], make_float2(wb.w,wb.w), acc[co][7]);
                }
            }
        }
    }

    // inverse transform A^T m + bias (validated in R8)
    const int x1 = x1g + x1l, x2 = x2g + x2l, x3 = x3g + x3l;
    const int base = ((x1*D2 + x2)*D3 + x3)*D4 + q*6;
    #pragma unroll
    for (int co = 0; co < 3; ++co) {
        float bsc = __ldg(bias + co);
        float2 bb = make_float2(bsc, bsc);
        float2* m = acc[co];
        float2 s1 = fadd2(m[1], m[2]), d1 = fsub2(m[1], m[2]);
        float2 s3 = fadd2(m[3], m[4]), d3 = fsub2(m[3], m[4]);
        float2 s5 = fadd2(m[5], m[6]), d5 = fsub2(m[5], m[6]);
        float2 y[6];
        y[0] = fadd2(fadd2(fadd2(m[0], s1), fadd2(s3, s5)), bb);
        y[1] = ffma2(d3, make_float2(2.f,2.f),
               ffma2(d5, make_float2(0.5f,0.5f), fadd2(d1, bb)));
        y[2] = ffma2(s3, make_float2(4.f,4.f),
               ffma2(s5, make_float2(0.25f,0.25f), fadd2(s1, bb)));
        y[3] = ffma2(d3, make_float2(8.f,8.f),
               ffma2(d5, make_float2(0.125f,0.125f), fadd2(d1, bb)));
        y[4] = ffma2(s3, make_float2(16.f,16.f),
               ffma2(s5, make_float2(0.0625f,0.0625f), fadd2(s1, bb)));
        y[5] = ffma2(d3, make_float2(32.f,32.f),
               ffma2(d5, make_float2(0.03125f,0.03125f),
               fadd2(fadd2(d1, m[7]), bb)));
        float4* op = (float4*)(out + co*NSP + base);
        #pragma unroll
        for (int j2 = 0; j2 < 3; ++j2)
            op[j2] = make_float4(y[2*j2].x, y[2*j2].y,
                                 y[2*j2+1].x, y[2*j2+1].y);
    }
}

// ---------------------------------------------------------------------------
// W1 conv: 3->3 ch, (3,3,3,1) taps, pad (1,1,1,0)  [UNCHANGED — R7 passing]
// ---------------------------------------------------------------------------
#define W1_W_F2     (81*4)
#define W1_STAGE_F2 (240*26)
#define W1_SMEM     ((W1_W_F2 + W1_STAGE_F2)*8)    // 52512 B

__global__ __launch_bounds__(256, 3) void w1_kernel(
    const float2* __restrict__ g,
    const float*  __restrict__ W,  const float* __restrict__ bias,
    float2* __restrict__ out)
{
    extern __shared__ float2 dsm[];
    float2* sW  = dsm;
    float2* sIn = dsm + W1_W_F2;

    const int tid = threadIdx.x;
    const int x3l = tid & 7;
    const int q   = (tid >> 3) & 3;
    const int x2l = (tid >> 5) & 3;
    const int x1l = tid >> 7;
    const int x1g = blockIdx.x * 2;
    const int x2g = blockIdx.y * 4;
    const int x3g = blockIdx.z * 8;

    for (int s = tid; s < 81*3; s += 256) {
        int grp = s / 3, co = s % 3;
        int ci = grp / 27, k = grp % 27;
        float w = W[(co*3 + ci)*27 + k];
        sW[grp*4 + co] = make_float2(w, w);
    }

    float2 acc[3][6];
    #pragma unroll
    for (int co = 0; co < 3; ++co) {
        float b = __ldg(bias + co);
        #pragma unroll
        for (int j = 0; j < 6; ++j) acc[co][j] = make_float2(b, b);
    }

    for (int ci = 0; ci < 3; ++ci) {
        const float2* __restrict__ src = g + ci * NSP;
        __syncthreads();
        for (int idx = tid; idx < 240*12; idx += 256) {
            int row = idx / 12, c = idx % 12;
            int p3 = row % 10; int t = row / 10; int p2 = t % 6; int p1 = t / 6;
            int g1 = x1g - 1 + p1, g2 = x2g - 1 + p2, g3 = x3g - 1 + p3;
            float4 v = make_float4(0.f, 0.f, 0.f, 0.f);
            if ((unsigned)g1 < (unsigned)D1 && (unsigned)g2 < (unsigned)D2 &&
                (unsigned)g3 < (unsigned)D3)
                v = ((const float4*)src)[((g1*D2 + g2)*D3 + g3)*12 + c];
            ((float4*)sIn)[row*13 + c] = v;
        }
        __syncthreads();

        const float2* wci = sW + ci * 108;
        #pragma unroll 1
        for (int k1 = 0; k1 < 3; ++k1) {
            #pragma unroll
            for (int k23 = 0; k23 < 9; ++k23) {
                const int k2 = k23 / 3, k3 = k23 % 3;
                const float4* ip = (const float4*)sIn
                    + (((x1l + k1)*6 + (x2l + k2))*10 + (x3l + k3))*13 + q*3;
                float4 a4[3];
                #pragma unroll
                for (int m = 0; m < 3; ++m) a4[m] = ip[m];
                const float2* uf = reinterpret_cast<const float2*>(a4);

                const float2* wp = wci + (k1*9 + k23)*4;
                float2 w0 = wp[0];
                float2 w1 = wp[1];
                float2 w2 = wp[2];
                #pragma unroll
                for (int j = 0; j < 6; ++j) {
                    acc[0][j] = ffma2(uf[j], w0, acc[0][j]);
                    acc[1][j] = ffma2(uf[j], w1, acc[1][j]);
                    acc[2][j] = ffma2(uf[j], w2, acc[2][j]);
                }
            }
        }
    }

    const int x1 = x1g + x1l, x2 = x2g + x2l, x3 = x3g + x3l;
    const int base = ((x1*D2 + x2)*D3 + x3)*D4 + q*6;
    #pragma unroll
    for (int co = 0; co < 3; ++co) {
        float4* op = (float4*)(out + co*NSP + base);
        #pragma unroll
        for (int j2 = 0; j2 < 3; ++j2)
            op[j2] = make_float4(acc[co][2*j2].x,   acc[co][2*j2].y,
                                 acc[co][2*j2+1].x, acc[co][2*j2+1].y);
    }
}

// ---------------------------------------------------------------------------
// Fused epilogue  [UNCHANGED — passing since R1]
// ---------------------------------------------------------------------------
__global__ void w2wd_kernel(
    const float2* __restrict__ t,  const float2* __restrict__ op,
    const float*  __restrict__ W2, const float* __restrict__ b2,
    const float*  __restrict__ Wd, const float* __restrict__ bd,
    float2* __restrict__ onew, float* __restrict__ ofinal, int final_layer)
{
    int i = blockIdx.x * blockDim.x + threadIdx.x;
    if (i >= NSP) return;
    int x4 = i % D4;

    float w2r[3][3][3], wdr[3][3];
    #pragma unroll
    for (int co = 0; co < 3; ++co) {
        #pragma unroll
        for (int ci = 0; ci < 3; ++ci) {
            #pragma unroll
            for (int k = 0; k < 3; ++k)
                w2r[co][ci][k] = W2[(co*3 + ci)*3 + k];
            wdr[co][ci] = Wd[co*3 + ci];
        }
    }

    float2 acc[3];
    #pragma unroll
    for (int co = 0; co < 3; ++co) {
        float b = b2[co] + bd[co];
        acc[co] = make_float2(b, b);
    }

    const float2 z = make_float2(0.f, 0.f);
    #pragma unroll
    for (int ci = 0; ci < 3; ++ci) {
        float2 tm = (x4 > 0)      ? t[ci*NSP + i - 1] : z;
        float2 t0 =                 t[ci*NSP + i];
        float2 tp = (x4 < D4 - 1) ? t[ci*NSP + i + 1] : z;
        float2 ov =                 op[ci*NSP + i];
        #pragma unroll
        for (int co = 0; co < 3; ++co) {
            float2 a = acc[co];
            a = ffma2(tm, make_float2(w2r[co][ci][0], w2r[co][ci][0]), a);
            a = ffma2(t0, make_float2(w2r[co][ci][1], w2r[co][ci][1]), a);
            a = ffma2(tp, make_float2(w2r[co][ci][2], w2r[co][ci][2]), a);
            a = ffma2(ov, make_float2(wdr[co][ci],    wdr[co][ci]),    a);
            acc[co] = a;
        }
    }

    if (final_layer) {
        #pragma unroll
        for (int co = 0; co < 3; ++co) {
            ofinal[co*NSP + i]      = acc[co].x;
            ofinal[CN + co*NSP + i] = acc[co].y;
        }
    } else {
        #pragma unroll
        for (int co = 0; co < 3; ++co)
            onew[co*NSP + i] = acc[co];
    }
}

// ---------------------------------------------------------------------------
// Driver
// ---------------------------------------------------------------------------
extern "C" void kernel_launch(void* const* d_in, const int* in_sizes, int n_in,
                              void* d_out, int out_size)
{
    const float* f   = (const float*)d_in[0];
    const float* bnd = (const float*)d_in[1];
    const float* Wg  = (const float*)d_in[2];
    const float* bg  = (const float*)d_in[3];
    const float* W1  = (const float*)d_in[4];
    const float* b1  = (const float*)d_in[5];
    const float* W2  = (const float*)d_in[6];
    const float* b2  = (const float*)d_in[7];
    const float* Wd  = (const float*)d_in[8];
    const float* bd  = (const float*)d_in[9];

    static bool attr_done = false;
    if (!attr_done) {
        cudaFuncSetAttribute(wg_kernel,
            cudaFuncAttributeMaxDynamicSharedMemorySize, WG_SMEM);
        cudaFuncSetAttribute(w1_kernel,
            cudaFuncAttributeMaxDynamicSharedMemorySize, W1_SMEM);
        attr_done = true;
    }

    float2 *fi, *bi, *gg, *tt, *oA, *oB, *ub;
    float *wtf;
    cudaGetSymbolAddress((void**)&fi, s_fi);
    cudaGetSymbolAddress((void**)&bi, s_bi);
    cudaGetSymbolAddress((void**)&gg, s_g);
    cudaGetSymbolAddress((void**)&tt, s_t);
    cudaGetSymbolAddress((void**)&oA, s_oA);
    cudaGetSymbolAddress((void**)&oB, s_oB);
    cudaGetSymbolAddress((void**)&ub, s_u);
    cudaGetSymbolAddress((void**)&wtf, s_wgtf);

    pack_kernel<<<(CN/4 + 255) / 256, 256>>>(
        (const float4*)f, (const float4*)bnd, (float4*)fi, (float4*)bi,
        Wg, wtf);

    // boundary channels transformed once -> u[3..5]
    bx_kernel<<<dim3(NROW/64, 3), 256>>>(bi, ub + (size_t)3*NROW*32);

    dim3 cgrid(D1/2, D2/4, D3/8);
    const float2* cur = fi;
    float2* outs[LAYERS] = {oA, oB, oA, nullptr};

    for (int i = 0; i < LAYERS; ++i) {
        bx_kernel<<<dim3(NROW/64, 3), 256>>>(cur, ub);   // cur -> u[0..2]
        wg_kernel<<<cgrid, 256, WG_SMEM>>>(
            ub, wtf + i*3888, bg + i*3, gg);
        w1_kernel<<<cgrid, 256, W1_SMEM>>>(
            gg, W1 + i*243, b1 + i*3, tt);
        w2wd_kernel<<<(NSP + 255) / 256, 256>>>(
            tt, cur, W2 + i*27, b2 + i*3, Wd + i*9, bd + i*3,
            outs[i], (float*)d_out, (i == LAYERS - 1) ? 1 : 0);
        cur = outs[i];
    }
}